// round 3
// baseline (speedup 1.0000x reference)
#include <cuda_runtime.h>
#include <math.h>

#define H 128
#define MAXN 100000
#define NGRAPH 100
#define SPLITS 8

// ---- scratch (static device globals; no runtime allocation) ----
__device__ float g_y[MAXN * H];     // y = (x*ns) @ W  (per layer)
__device__ float g_agg[MAXN * H];   // agg = y + sum_edges y[src]
__device__ float g_w[MAXN];         // sigmoid gate
__device__ int   g_odeg[MAXN];
__device__ int   g_ideg[MAXN];
__device__ float g_ns[MAXN];        // rsqrt(out_deg+1)
__device__ float g_nd[MAXN];        // rsqrt(in_deg+1)

// ---- init: zero degree counters and output ----
__global__ void k_init(float* out, int outn, int N) {
    int i = blockIdx.x * blockDim.x + threadIdx.x;
    if (i < outn) out[i] = 0.0f;
    if (i < N) { g_odeg[i] = 0; g_ideg[i] = 0; }
}

// ---- degrees ----
__global__ void k_deg(const int* __restrict__ src, const int* __restrict__ dst, int E) {
    int e = blockIdx.x * blockDim.x + threadIdx.x;
    if (e < E) {
        atomicAdd(&g_odeg[src[e]], 1);
        atomicAdd(&g_ideg[dst[e]], 1);
    }
}

__global__ void k_norm(int N) {
    int i = blockIdx.x * blockDim.x + threadIdx.x;
    if (i < N) {
        g_ns[i] = rsqrtf((float)(g_odeg[i] + 1));   // +1 self loop; always >= 1
        g_nd[i] = rsqrtf((float)(g_ideg[i] + 1));
    }
}

// ---- GEMM: out[r][c] = sum_k x[r][k] * W[k][c];  writes y and agg (=y, self loop) ----
// mode 0: x = Xext[r][k] * ns[r]                (layer 1, Xext = node_feats)
// mode 1: x = relu(g_agg[r][k]*nd[r]+bias[k]) * ns[r]   (layers 2,3; in-place safe: row-local)
__global__ void __launch_bounds__(256) k_gemm(const float* Xext,
                                              const float* __restrict__ Wm,
                                              const float* __restrict__ bias,
                                              int N, int mode) {
    __shared__ float a_s[16][H + 4];  // transposed x chunk: a_s[k][row]
    __shared__ float b_s[16][H];      // W chunk: b_s[k][col]

    const int tid = threadIdx.x;
    const int tx = tid & 15;          // col group
    const int ty = tid >> 4;          // row group
    const int r0 = blockIdx.x * H;    // 128 rows per block

    const float* X = (mode == 0) ? Xext : g_agg;

    float acc[8][8];
#pragma unroll
    for (int i = 0; i < 8; i++)
#pragma unroll
        for (int j = 0; j < 8; j++) acc[i][j] = 0.0f;

    for (int kb = 0; kb < H; kb += 16) {
        // load W chunk (rows kb..kb+15, all 128 cols), coalesced float4
        {
            int t = tid;
#pragma unroll
            for (int rep = 0; rep < 2; rep++) {
                int kk = t >> 5;              // 0..15
                int c4 = (t & 31) * 4;
                float4 v = *(const float4*)(Wm + (kb + kk) * H + c4);
                *(float4*)(&b_s[kk][c4]) = v;
                t += 256;
            }
        }
        // load x chunk with fused epilogue, store transposed
        {
#pragma unroll
            for (int rep = 0; rep < 2; rep++) {
                int rr = (tid >> 2) + rep * 64;     // 0..127
                int kk4 = (tid & 3) * 4;            // 0,4,8,12
                int r = r0 + rr;
                float4 v = make_float4(0.f, 0.f, 0.f, 0.f);
                if (r < N) v = *(const float4*)(X + (size_t)r * H + kb + kk4);
                float vv[4] = {v.x, v.y, v.z, v.w};
                if (mode == 1) {
                    float nd = (r < N) ? g_nd[r] : 0.0f;
#pragma unroll
                    for (int i = 0; i < 4; i++)
                        vv[i] = fmaxf(fmaf(vv[i], nd, bias[kb + kk4 + i]), 0.0f);
                }
                float ns = (r < N) ? g_ns[r] : 0.0f;
#pragma unroll
                for (int i = 0; i < 4; i++) a_s[kk4 + i][rr] = vv[i] * ns;
            }
        }
        __syncthreads();

#pragma unroll
        for (int k = 0; k < 16; k++) {
            float af[8], bf[8];
            *(float4*)(af)     = *(const float4*)(&a_s[k][ty * 4]);
            *(float4*)(af + 4) = *(const float4*)(&a_s[k][64 + ty * 4]);
            *(float4*)(bf)     = *(const float4*)(&b_s[k][tx * 4]);
            *(float4*)(bf + 4) = *(const float4*)(&b_s[k][64 + tx * 4]);
#pragma unroll
            for (int i = 0; i < 8; i++)
#pragma unroll
                for (int j = 0; j < 8; j++) acc[i][j] = fmaf(af[i], bf[j], acc[i][j]);
        }
        __syncthreads();
    }

    // store y and agg (agg initialized with self-loop contribution = y)
#pragma unroll
    for (int i = 0; i < 8; i++) {
        int rr = (i < 4) ? (ty * 4 + i) : (64 + ty * 4 + (i - 4));
        int r = r0 + rr;
        if (r < N) {
            float4 v0 = make_float4(acc[i][0], acc[i][1], acc[i][2], acc[i][3]);
            float4 v1 = make_float4(acc[i][4], acc[i][5], acc[i][6], acc[i][7]);
            size_t base = (size_t)r * H;
            *(float4*)(g_y + base + tx * 4) = v0;
            *(float4*)(g_y + base + 64 + tx * 4) = v1;
            *(float4*)(g_agg + base + tx * 4) = v0;
            *(float4*)(g_agg + base + 64 + tx * 4) = v1;
        }
    }
}

// ---- edge scatter: agg[dst] += y[src], one warp per edge, vector red ----
__global__ void __launch_bounds__(256) k_scatter(const int* __restrict__ src,
                                                 const int* __restrict__ dst, int E) {
    int warp = (blockIdx.x * blockDim.x + threadIdx.x) >> 5;
    int lane = threadIdx.x & 31;
    if (warp >= E) return;
    int s = __ldg(src + warp);
    int d = __ldg(dst + warp);
    float4 v = *(const float4*)(g_y + (size_t)s * H + lane * 4);
    float* p = g_agg + (size_t)d * H + lane * 4;
    asm volatile("red.global.add.v4.f32 [%0], {%1,%2,%3,%4};"
                 :: "l"(p), "f"(v.x), "f"(v.y), "f"(v.z), "f"(v.w) : "memory");
}

// ---- per-node: h3 = relu(agg*nd + b3) -> g_y;  w = sigmoid(h3 . Wp + bp) ----
__global__ void __launch_bounds__(256) k_node(const float* __restrict__ b3,
                                              const float* __restrict__ Wp,
                                              const float* __restrict__ bp, int N) {
    int n = (blockIdx.x * blockDim.x + threadIdx.x) >> 5;
    int lane = threadIdx.x & 31;
    if (n >= N) return;
    float nd = g_nd[n];
    float4 v = *(const float4*)(g_agg + (size_t)n * H + lane * 4);
    float4 b = *(const float4*)(b3 + lane * 4);
    float h0 = fmaxf(fmaf(v.x, nd, b.x), 0.0f);
    float h1 = fmaxf(fmaf(v.y, nd, b.y), 0.0f);
    float h2 = fmaxf(fmaf(v.z, nd, b.z), 0.0f);
    float h3v = fmaxf(fmaf(v.w, nd, b.w), 0.0f);
    *(float4*)(g_y + (size_t)n * H + lane * 4) = make_float4(h0, h1, h2, h3v);
    float4 wp = *(const float4*)(Wp + lane * 4);
    float t = h0 * wp.x + h1 * wp.y + h2 * wp.z + h3v * wp.w;
#pragma unroll
    for (int o = 16; o; o >>= 1) t += __shfl_xor_sync(0xffffffffu, t, o);
    if (lane == 0) g_w[n] = 1.0f / (1.0f + expf(-(t + bp[0])));
}

// ---- pooling: per (graph, split) block; graph_ids sorted -> binary search range ----
__global__ void __launch_bounds__(128) k_pool(const int* __restrict__ gid, int N,
                                              float* __restrict__ out) {
    int g = blockIdx.x / SPLITS;
    int sp = blockIdx.x % SPLITS;
    int c = threadIdx.x;

    int lo = 0, hi = N;
    while (lo < hi) { int m = (lo + hi) >> 1; if (gid[m] < g) lo = m + 1; else hi = m; }
    int start = lo;
    lo = start; hi = N;
    while (lo < hi) { int m = (lo + hi) >> 1; if (gid[m] <= g) lo = m + 1; else hi = m; }
    int end = lo;

    int cnt = end - start;
    int per = (cnt + SPLITS - 1) / SPLITS;
    int s = start + sp * per;
    int e = min(end, s + per);
    if (s >= e) return;

    float sum = 0.0f, mx = 0.0f;
    for (int n = s; n < e; n++) {
        float h = g_y[(size_t)n * H + c];
        float wv = g_w[n];
        sum = fmaf(h, wv, sum);
        mx = fmaxf(mx, h);
    }
    atomicAdd(&out[g * (2 * H) + c], sum);
    atomicMax((int*)&out[g * (2 * H) + H + c], __float_as_int(mx));  // relu >= 0: int order == float order
}

extern "C" void kernel_launch(void* const* d_in, const int* in_sizes, int n_in,
                              void* d_out, int out_size) {
    const float* node = (const float*)d_in[0];
    const int* src = (const int*)d_in[1];
    const int* dst = (const int*)d_in[2];
    const int* gid = (const int*)d_in[3];
    const float* W1 = (const float*)d_in[4];
    const float* b1 = (const float*)d_in[5];
    const float* W2 = (const float*)d_in[6];
    const float* b2 = (const float*)d_in[7];
    const float* W3 = (const float*)d_in[8];
    const float* b3 = (const float*)d_in[9];
    const float* Wp = (const float*)d_in[10];
    const float* bp = (const float*)d_in[11];
    float* out = (float*)d_out;

    int N = in_sizes[0] / H;
    int E = in_sizes[1];

    int initn = (out_size > N) ? out_size : N;
    k_init<<<(initn + 255) / 256, 256>>>(out, out_size, N);
    k_deg<<<(E + 255) / 256, 256>>>(src, dst, E);
    k_norm<<<(N + 255) / 256, 256>>>(N);

    int gb = (N + H - 1) / H;
    int sb = (E * 8 + 63) / 64;  // E warps, 8 warps/block

    // layer 1
    k_gemm<<<gb, 256>>>(node, W1, nullptr, N, 0);
    k_scatter<<<sb, 256>>>(src, dst, E);
    // layer 2
    k_gemm<<<gb, 256>>>(nullptr, W2, b1, N, 1);
    k_scatter<<<sb, 256>>>(src, dst, E);
    // layer 3
    k_gemm<<<gb, 256>>>(nullptr, W3, b2, N, 1);
    k_scatter<<<sb, 256>>>(src, dst, E);

    // epilogue + gating
    k_node<<<(N * 32 + 255) / 256, 256>>>(b3, Wp, bp, N);
    // pooling
    k_pool<<<NGRAPH * SPLITS, 128>>>(gid, N, out);
}

// round 5
// speedup vs baseline: 1.0442x; 1.0442x over previous
#include <cuda_runtime.h>
#include <math.h>

#define H 128
#define MAXN 100000
#define MAXE 1600000
#define NGRAPH 100
#define SPLITS 8
#define SCAN_T 1024

// ---- scratch (static device globals; no runtime allocation) ----
__device__ float g_y[MAXN * H];     // y = (x*ns) @ W  (per layer)
__device__ float g_agg[MAXN * H];   // agg = y_self + sum_edges y[src]
__device__ float g_w[MAXN];         // sigmoid gate
__device__ int   g_odeg[MAXN];
__device__ int   g_ideg[MAXN];
__device__ float g_ns[MAXN];        // rsqrt(out_deg+1)
__device__ float g_nd[MAXN];        // rsqrt(in_deg+1)
__device__ int   g_off[MAXN + 1];   // CSR offsets by dst
__device__ int   g_cur[MAXN];       // fill cursors
__device__ int   g_esrc[MAXE];      // src ids sorted by dst

// ---- init: zero degree counters, cursors, and output ----
__global__ void k_init(float* out, int outn, int N) {
    int i = blockIdx.x * blockDim.x + threadIdx.x;
    if (i < outn) out[i] = 0.0f;
    if (i < N) { g_odeg[i] = 0; g_ideg[i] = 0; g_cur[i] = 0; }
}

// ---- degrees ----
__global__ void k_deg(const int* __restrict__ src, const int* __restrict__ dst, int E) {
    int e = blockIdx.x * blockDim.x + threadIdx.x;
    if (e < E) {
        atomicAdd(&g_odeg[src[e]], 1);
        atomicAdd(&g_ideg[dst[e]], 1);
    }
}

__global__ void k_norm(int N) {
    int i = blockIdx.x * blockDim.x + threadIdx.x;
    if (i < N) {
        g_ns[i] = rsqrtf((float)(g_odeg[i] + 1));   // +1 self loop
        g_nd[i] = rsqrtf((float)(g_ideg[i] + 1));
    }
}

// ---- exclusive prefix scan of g_ideg -> g_off (single block) ----
__global__ void __launch_bounds__(SCAN_T) k_scan(int N) {
    __shared__ int s[SCAN_T];
    int t = threadIdx.x;
    int C = (N + SCAN_T - 1) / SCAN_T;
    int b = t * C, e = min(N, b + C);
    int sum = 0;
    for (int i = b; i < e; i++) sum += g_ideg[i];
    s[t] = sum;
    __syncthreads();
    for (int o = 1; o < SCAN_T; o <<= 1) {
        int v = (t >= o) ? s[t - o] : 0;
        __syncthreads();
        s[t] += v;
        __syncthreads();
    }
    int run = (t == 0) ? 0 : s[t - 1];
    for (int i = b; i < e; i++) { int v = g_ideg[i]; g_off[i] = run; run += v; }
    if (t == SCAN_T - 1) g_off[N] = run;
}

// ---- fill CSR: place src ids into dst buckets ----
__global__ void k_fill(const int* __restrict__ src, const int* __restrict__ dst, int E) {
    int e = blockIdx.x * blockDim.x + threadIdx.x;
    if (e < E) {
        int d = dst[e];
        int p = atomicAdd(&g_cur[d], 1);
        g_esrc[g_off[d] + p] = src[e];
    }
}

// ---- GEMM: g_y[r][c] = sum_k x[r][k] * W[k][c]  (y only; agg produced by gather) ----
// mode 0: x = Xext[r][k] * ns[r]
// mode 1: x = relu(g_agg[r][k]*nd[r]+bias[k]) * ns[r]
__global__ void __launch_bounds__(256) k_gemm(const float* Xext,
                                              const float* __restrict__ Wm,
                                              const float* __restrict__ bias,
                                              int N, int mode) {
    __shared__ float a_s[16][H + 4];
    __shared__ float b_s[16][H];

    const int tid = threadIdx.x;
    const int tx = tid & 15;
    const int ty = tid >> 4;
    const int r0 = blockIdx.x * H;

    const float* X = (mode == 0) ? Xext : g_agg;

    float acc[8][8];
#pragma unroll
    for (int i = 0; i < 8; i++)
#pragma unroll
        for (int j = 0; j < 8; j++) acc[i][j] = 0.0f;

    for (int kb = 0; kb < H; kb += 16) {
        {
            int t = tid;
#pragma unroll
            for (int rep = 0; rep < 2; rep++) {
                int kk = t >> 5;
                int c4 = (t & 31) * 4;
                float4 v = *(const float4*)(Wm + (kb + kk) * H + c4);
                *(float4*)(&b_s[kk][c4]) = v;
                t += 256;
            }
        }
        {
#pragma unroll
            for (int rep = 0; rep < 2; rep++) {
                int rr = (tid >> 2) + rep * 64;
                int kk4 = (tid & 3) * 4;
                int r = r0 + rr;
                float4 v = make_float4(0.f, 0.f, 0.f, 0.f);
                if (r < N) v = *(const float4*)(X + (size_t)r * H + kb + kk4);
                float vv[4] = {v.x, v.y, v.z, v.w};
                if (mode == 1) {
                    float nd = (r < N) ? g_nd[r] : 0.0f;
#pragma unroll
                    for (int i = 0; i < 4; i++)
                        vv[i] = fmaxf(fmaf(vv[i], nd, bias[kb + kk4 + i]), 0.0f);
                }
                float ns = (r < N) ? g_ns[r] : 0.0f;
#pragma unroll
                for (int i = 0; i < 4; i++) a_s[kk4 + i][rr] = vv[i] * ns;
            }
        }
        __syncthreads();

#pragma unroll
        for (int k = 0; k < 16; k++) {
            float af[8], bf[8];
            *(float4*)(af)     = *(const float4*)(&a_s[k][ty * 4]);
            *(float4*)(af + 4) = *(const float4*)(&a_s[k][64 + ty * 4]);
            *(float4*)(bf)     = *(const float4*)(&b_s[k][tx * 4]);
            *(float4*)(bf + 4) = *(const float4*)(&b_s[k][64 + tx * 4]);
#pragma unroll
            for (int i = 0; i < 8; i++)
#pragma unroll
                for (int j = 0; j < 8; j++) acc[i][j] = fmaf(af[i], bf[j], acc[i][j]);
        }
        __syncthreads();
    }

#pragma unroll
    for (int i = 0; i < 8; i++) {
        int rr = (i < 4) ? (ty * 4 + i) : (64 + ty * 4 + (i - 4));
        int r = r0 + rr;
        if (r < N) {
            size_t base = (size_t)r * H;
            *(float4*)(g_y + base + tx * 4) =
                make_float4(acc[i][0], acc[i][1], acc[i][2], acc[i][3]);
            *(float4*)(g_y + base + 64 + tx * 4) =
                make_float4(acc[i][4], acc[i][5], acc[i][6], acc[i][7]);
        }
    }
}

// ---- gather: agg[d] = y[d] + sum_{e in CSR[d]} y[src[e]]; exclusive, no atomics ----
__global__ void __launch_bounds__(256) k_gather(int N) {
    int w = (blockIdx.x * blockDim.x + threadIdx.x) >> 5;
    int lane = threadIdx.x & 31;
    if (w >= N) return;
    int s = g_off[w], e = g_off[w + 1];
    const float4* __restrict__ Y = (const float4*)g_y;
    float4 acc = Y[(size_t)w * 32 + lane];     // self loop
    int i = s;
    for (; i + 4 <= e; i += 4) {
        int i0 = g_esrc[i], i1 = g_esrc[i + 1], i2 = g_esrc[i + 2], i3 = g_esrc[i + 3];
        float4 v0 = Y[(size_t)i0 * 32 + lane];
        float4 v1 = Y[(size_t)i1 * 32 + lane];
        float4 v2 = Y[(size_t)i2 * 32 + lane];
        float4 v3 = Y[(size_t)i3 * 32 + lane];
        acc.x += (v0.x + v1.x) + (v2.x + v3.x);
        acc.y += (v0.y + v1.y) + (v2.y + v3.y);
        acc.z += (v0.z + v1.z) + (v2.z + v3.z);
        acc.w += (v0.w + v1.w) + (v2.w + v3.w);
    }
    for (; i < e; i++) {
        float4 v = Y[(size_t)g_esrc[i] * 32 + lane];
        acc.x += v.x; acc.y += v.y; acc.z += v.z; acc.w += v.w;
    }
    ((float4*)g_agg)[(size_t)w * 32 + lane] = acc;
}

// ---- per-node: h3 = relu(agg*nd + b3) -> g_y;  w = sigmoid(h3 . Wp + bp) ----
__global__ void __launch_bounds__(256) k_node(const float* __restrict__ b3,
                                              const float* __restrict__ Wp,
                                              const float* __restrict__ bp, int N) {
    int n = (blockIdx.x * blockDim.x + threadIdx.x) >> 5;
    int lane = threadIdx.x & 31;
    if (n >= N) return;
    float nd = g_nd[n];
    float4 v = *(const float4*)(g_agg + (size_t)n * H + lane * 4);
    float4 b = *(const float4*)(b3 + lane * 4);
    float h0 = fmaxf(fmaf(v.x, nd, b.x), 0.0f);
    float h1 = fmaxf(fmaf(v.y, nd, b.y), 0.0f);
    float h2 = fmaxf(fmaf(v.z, nd, b.z), 0.0f);
    float h3v = fmaxf(fmaf(v.w, nd, b.w), 0.0f);
    *(float4*)(g_y + (size_t)n * H + lane * 4) = make_float4(h0, h1, h2, h3v);
    float4 wp = *(const float4*)(Wp + lane * 4);
    float t = h0 * wp.x + h1 * wp.y + h2 * wp.z + h3v * wp.w;
#pragma unroll
    for (int o = 16; o; o >>= 1) t += __shfl_xor_sync(0xffffffffu, t, o);
    if (lane == 0) g_w[n] = 1.0f / (1.0f + expf(-(t + bp[0])));
}

// ---- pooling: per (graph, split) block; graph_ids sorted -> binary search range ----
__global__ void __launch_bounds__(128) k_pool(const int* __restrict__ gid, int N,
                                              float* __restrict__ out) {
    int g = blockIdx.x / SPLITS;
    int sp = blockIdx.x % SPLITS;
    int c = threadIdx.x;

    int lo = 0, hi = N;
    while (lo < hi) { int m = (lo + hi) >> 1; if (gid[m] < g) lo = m + 1; else hi = m; }
    int start = lo;
    lo = start; hi = N;
    while (lo < hi) { int m = (lo + hi) >> 1; if (gid[m] <= g) lo = m + 1; else hi = m; }
    int end = lo;

    int cnt = end - start;
    int per = (cnt + SPLITS - 1) / SPLITS;
    int s = start + sp * per;
    int e = min(end, s + per);
    if (s >= e) return;

    float sum = 0.0f, mx = 0.0f;
    for (int n = s; n < e; n++) {
        float h = g_y[(size_t)n * H + c];
        float wv = g_w[n];
        sum = fmaf(h, wv, sum);
        mx = fmaxf(mx, h);
    }
    atomicAdd(&out[g * (2 * H) + c], sum);
    atomicMax((int*)&out[g * (2 * H) + H + c], __float_as_int(mx));  // relu >= 0
}

extern "C" void kernel_launch(void* const* d_in, const int* in_sizes, int n_in,
                              void* d_out, int out_size) {
    const float* node = (const float*)d_in[0];
    const int* src = (const int*)d_in[1];
    const int* dst = (const int*)d_in[2];
    const int* gid = (const int*)d_in[3];
    const float* W1 = (const float*)d_in[4];
    const float* b1 = (const float*)d_in[5];
    const float* W2 = (const float*)d_in[6];
    const float* b2 = (const float*)d_in[7];
    const float* W3 = (const float*)d_in[8];
    const float* b3 = (const float*)d_in[9];
    const float* Wp = (const float*)d_in[10];
    const float* bp = (const float*)d_in[11];
    float* out = (float*)d_out;

    int N = in_sizes[0] / H;
    int E = in_sizes[1];

    int initn = (out_size > N) ? out_size : N;
    k_init<<<(initn + 255) / 256, 256>>>(out, out_size, N);
    k_deg<<<(E + 255) / 256, 256>>>(src, dst, E);
    k_norm<<<(N + 255) / 256, 256>>>(N);
    k_scan<<<1, SCAN_T>>>(N);
    k_fill<<<(E + 255) / 256, 256>>>(src, dst, E);

    int gb = (N + H - 1) / H;
    int wb = (N * 32 + 255) / 256;

    // layer 1
    k_gemm<<<gb, 256>>>(node, W1, nullptr, N, 0);
    k_gather<<<wb, 256>>>(N);
    // layer 2
    k_gemm<<<gb, 256>>>(nullptr, W2, b1, N, 1);
    k_gather<<<wb, 256>>>(N);
    // layer 3
    k_gemm<<<gb, 256>>>(nullptr, W3, b2, N, 1);
    k_gather<<<wb, 256>>>(N);

    // epilogue + gating
    k_node<<<wb, 256>>>(b3, Wp, bp, N);
    // pooling
    k_pool<<<NGRAPH * SPLITS, 128>>>(gid, N, out);
}

// round 6
// speedup vs baseline: 1.7987x; 1.7225x over previous
#include <cuda_runtime.h>
#include <math.h>

#define H 128
#define MAXN 100000
#define MAXE 1600000
#define NGRAPH 100
#define SPLITS 8
#define SCAN_CHUNK 2048   // elems per scan block (256 thr * 8)
#define MAXBLK 64         // max scan blocks (ceil(100000/2048)=49)

// ---- scratch (static device globals; no runtime allocation) ----
__device__ float g_y[MAXN * H];     // y = (x*ns) @ W  (per layer)
__device__ float g_agg[MAXN * H];   // agg (layers 1,2) / h3 (final)
__device__ float g_w[MAXN];         // sigmoid gate
__device__ int   g_odeg[MAXN];
__device__ int   g_ideg[MAXN];
__device__ float g_ns[MAXN];        // rsqrt(out_deg+1)
__device__ float g_nd[MAXN];        // rsqrt(in_deg+1)
__device__ int   g_off[MAXN + 1];   // CSR offsets by dst
__device__ int   g_cur[MAXN];       // fill cursors
__device__ int   g_esrc[MAXE];      // src ids sorted by dst
__device__ int   g_bsum[MAXBLK];    // scan block sums

// ---- init: zero degree counters, cursors, and output ----
__global__ void k_init(float* out, int outn, int N) {
    int i = blockIdx.x * blockDim.x + threadIdx.x;
    if (i < outn) out[i] = 0.0f;
    if (i < N) { g_odeg[i] = 0; g_ideg[i] = 0; g_cur[i] = 0; }
}

// ---- degrees ----
__global__ void k_deg(const int* __restrict__ src, const int* __restrict__ dst, int E) {
    int e = blockIdx.x * blockDim.x + threadIdx.x;
    if (e < E) {
        atomicAdd(&g_odeg[src[e]], 1);
        atomicAdd(&g_ideg[dst[e]], 1);
    }
}

__global__ void k_norm(int N) {
    int i = blockIdx.x * blockDim.x + threadIdx.x;
    if (i < N) {
        g_ns[i] = rsqrtf((float)(g_odeg[i] + 1));   // +1 self loop
        g_nd[i] = rsqrtf((float)(g_ideg[i] + 1));
    }
}

// ---- scan phase 1: per-block sums of g_ideg ----
__global__ void __launch_bounds__(256) k_scan1(int N) {
    __shared__ int sh[8];
    int b = blockIdx.x, t = threadIdx.x;
    int base = b * SCAN_CHUNK + t * 8;
    int s = 0;
#pragma unroll
    for (int j = 0; j < 8; j++) { int idx = base + j; if (idx < N) s += g_ideg[idx]; }
#pragma unroll
    for (int o = 16; o; o >>= 1) s += __shfl_xor_sync(0xffffffffu, s, o);
    if ((t & 31) == 0) sh[t >> 5] = s;
    __syncthreads();
    if (t == 0) {
        int tot = 0;
#pragma unroll
        for (int w = 0; w < 8; w++) tot += sh[w];
        g_bsum[b] = tot;
    }
}

// ---- scan phase 2: exclusive scan of block sums (single tiny block) ----
__global__ void __launch_bounds__(MAXBLK) k_scan2(int NB, int N) {
    __shared__ int sh[MAXBLK];
    int t = threadIdx.x;
    int v = (t < NB) ? g_bsum[t] : 0;
    sh[t] = v;
    __syncthreads();
#pragma unroll
    for (int o = 1; o < MAXBLK; o <<= 1) {
        int x = (t >= o) ? sh[t - o] : 0;
        __syncthreads();
        sh[t] += x;
        __syncthreads();
    }
    if (t < NB) g_bsum[t] = sh[t] - v;          // exclusive
    if (t == MAXBLK - 1) g_off[N] = sh[t];      // total
}

// ---- scan phase 3: distribute; write g_off ----
__global__ void __launch_bounds__(256) k_scan3(int N) {
    __shared__ int sh[256];
    int b = blockIdx.x, t = threadIdx.x;
    int base = b * SCAN_CHUNK + t * 8;
    int v[8], pre[8];
    int s = 0;
#pragma unroll
    for (int j = 0; j < 8; j++) {
        int idx = base + j;
        v[j] = (idx < N) ? g_ideg[idx] : 0;
        pre[j] = s;
        s += v[j];
    }
    sh[t] = s;
    __syncthreads();
#pragma unroll
    for (int o = 1; o < 256; o <<= 1) {
        int x = (t >= o) ? sh[t - o] : 0;
        __syncthreads();
        sh[t] += x;
        __syncthreads();
    }
    int tpre = ((t == 0) ? 0 : sh[t - 1]) + g_bsum[b];
#pragma unroll
    for (int j = 0; j < 8; j++) {
        int idx = base + j;
        if (idx < N) g_off[idx] = tpre + pre[j];
    }
}

// ---- fill CSR: place src ids into dst buckets ----
__global__ void k_fill(const int* __restrict__ src, const int* __restrict__ dst, int E) {
    int e = blockIdx.x * blockDim.x + threadIdx.x;
    if (e < E) {
        int d = dst[e];
        int p = atomicAdd(&g_cur[d], 1);
        g_esrc[g_off[d] + p] = src[e];
    }
}

// ---- GEMM: g_y[r][c] = sum_k x[r][k] * W[k][c] ----
// mode 0: x = Xext[r][k] * ns[r]
// mode 1: x = relu(g_agg[r][k]*nd[r]+bias[k]) * ns[r]
__global__ void __launch_bounds__(256) k_gemm(const float* Xext,
                                              const float* __restrict__ Wm,
                                              const float* __restrict__ bias,
                                              int N, int mode) {
    __shared__ float a_s[16][H + 4];
    __shared__ float b_s[16][H];

    const int tid = threadIdx.x;
    const int tx = tid & 15;
    const int ty = tid >> 4;
    const int r0 = blockIdx.x * H;

    const float* X = (mode == 0) ? Xext : g_agg;

    float acc[8][8];
#pragma unroll
    for (int i = 0; i < 8; i++)
#pragma unroll
        for (int j = 0; j < 8; j++) acc[i][j] = 0.0f;

    for (int kb = 0; kb < H; kb += 16) {
        {
            int t = tid;
#pragma unroll
            for (int rep = 0; rep < 2; rep++) {
                int kk = t >> 5;
                int c4 = (t & 31) * 4;
                float4 v = *(const float4*)(Wm + (kb + kk) * H + c4);
                *(float4*)(&b_s[kk][c4]) = v;
                t += 256;
            }
        }
        {
#pragma unroll
            for (int rep = 0; rep < 2; rep++) {
                int rr = (tid >> 2) + rep * 64;
                int kk4 = (tid & 3) * 4;
                int r = r0 + rr;
                float4 v = make_float4(0.f, 0.f, 0.f, 0.f);
                if (r < N) v = *(const float4*)(X + (size_t)r * H + kb + kk4);
                float vv[4] = {v.x, v.y, v.z, v.w};
                if (mode == 1) {
                    float nd = (r < N) ? g_nd[r] : 0.0f;
#pragma unroll
                    for (int i = 0; i < 4; i++)
                        vv[i] = fmaxf(fmaf(vv[i], nd, bias[kb + kk4 + i]), 0.0f);
                }
                float ns = (r < N) ? g_ns[r] : 0.0f;
#pragma unroll
                for (int i = 0; i < 4; i++) a_s[kk4 + i][rr] = vv[i] * ns;
            }
        }
        __syncthreads();

#pragma unroll
        for (int k = 0; k < 16; k++) {
            float af[8], bf[8];
            *(float4*)(af)     = *(const float4*)(&a_s[k][ty * 4]);
            *(float4*)(af + 4) = *(const float4*)(&a_s[k][64 + ty * 4]);
            *(float4*)(bf)     = *(const float4*)(&b_s[k][tx * 4]);
            *(float4*)(bf + 4) = *(const float4*)(&b_s[k][64 + tx * 4]);
#pragma unroll
            for (int i = 0; i < 8; i++)
#pragma unroll
                for (int j = 0; j < 8; j++) acc[i][j] = fmaf(af[i], bf[j], acc[i][j]);
        }
        __syncthreads();
    }

#pragma unroll
    for (int i = 0; i < 8; i++) {
        int rr = (i < 4) ? (ty * 4 + i) : (64 + ty * 4 + (i - 4));
        int r = r0 + rr;
        if (r < N) {
            size_t base = (size_t)r * H;
            *(float4*)(g_y + base + tx * 4) =
                make_float4(acc[i][0], acc[i][1], acc[i][2], acc[i][3]);
            *(float4*)(g_y + base + 64 + tx * 4) =
                make_float4(acc[i][4], acc[i][5], acc[i][6], acc[i][7]);
        }
    }
}

// ---- gather: acc = y[d] + sum_{e in CSR[d]} y[src[e]] (registers only) ----
// fin=0: store acc -> g_agg
// fin=1: h = relu(acc*nd + b3) -> g_agg; gate w = sigmoid(h . Wp + bp) -> g_w
__global__ void __launch_bounds__(256) k_gather(int N, int fin,
                                                const float* __restrict__ b3,
                                                const float* __restrict__ Wp,
                                                const float* __restrict__ bp) {
    int w = (blockIdx.x * blockDim.x + threadIdx.x) >> 5;
    int lane = threadIdx.x & 31;
    if (w >= N) return;
    int s = g_off[w], e = g_off[w + 1];
    const float4* __restrict__ Y = (const float4*)g_y;
    float4 acc = __ldg(Y + (size_t)w * 32 + lane);     // self loop
    int i = s;
    for (; i + 8 <= e; i += 8) {
        int idx[8];
#pragma unroll
        for (int j = 0; j < 8; j++) idx[j] = __ldg(g_esrc + i + j);
        float4 v[8];
#pragma unroll
        for (int j = 0; j < 8; j++) v[j] = __ldg(Y + (size_t)idx[j] * 32 + lane);
#pragma unroll
        for (int j = 0; j < 8; j++) {
            acc.x += v[j].x; acc.y += v[j].y; acc.z += v[j].z; acc.w += v[j].w;
        }
    }
    for (; i + 2 <= e; i += 2) {
        int i0 = __ldg(g_esrc + i), i1 = __ldg(g_esrc + i + 1);
        float4 v0 = __ldg(Y + (size_t)i0 * 32 + lane);
        float4 v1 = __ldg(Y + (size_t)i1 * 32 + lane);
        acc.x += v0.x + v1.x; acc.y += v0.y + v1.y;
        acc.z += v0.z + v1.z; acc.w += v0.w + v1.w;
    }
    if (i < e) {
        float4 v = __ldg(Y + (size_t)__ldg(g_esrc + i) * 32 + lane);
        acc.x += v.x; acc.y += v.y; acc.z += v.z; acc.w += v.w;
    }
    if (!fin) {
        ((float4*)g_agg)[(size_t)w * 32 + lane] = acc;
    } else {
        float nd = g_nd[w];
        float4 b = __ldg((const float4*)b3 + lane);
        float h0 = fmaxf(fmaf(acc.x, nd, b.x), 0.0f);
        float h1 = fmaxf(fmaf(acc.y, nd, b.y), 0.0f);
        float h2 = fmaxf(fmaf(acc.z, nd, b.z), 0.0f);
        float h3 = fmaxf(fmaf(acc.w, nd, b.w), 0.0f);
        ((float4*)g_agg)[(size_t)w * 32 + lane] = make_float4(h0, h1, h2, h3);
        float4 wp = __ldg((const float4*)Wp + lane);
        float t = h0 * wp.x + h1 * wp.y + h2 * wp.z + h3 * wp.w;
#pragma unroll
        for (int o = 16; o; o >>= 1) t += __shfl_xor_sync(0xffffffffu, t, o);
        if (lane == 0) g_w[w] = 1.0f / (1.0f + expf(-(t + bp[0])));
    }
}

// ---- pooling: per (graph, split) block; reads h from g_agg ----
__global__ void __launch_bounds__(128) k_pool(const int* __restrict__ gid, int N,
                                              float* __restrict__ out) {
    int g = blockIdx.x / SPLITS;
    int sp = blockIdx.x % SPLITS;
    int c = threadIdx.x;

    int lo = 0, hi = N;
    while (lo < hi) { int m = (lo + hi) >> 1; if (gid[m] < g) lo = m + 1; else hi = m; }
    int start = lo;
    lo = start; hi = N;
    while (lo < hi) { int m = (lo + hi) >> 1; if (gid[m] <= g) lo = m + 1; else hi = m; }
    int end = lo;

    int cnt = end - start;
    int per = (cnt + SPLITS - 1) / SPLITS;
    int s = start + sp * per;
    int e = min(end, s + per);
    if (s >= e) return;

    float sum = 0.0f, mx = 0.0f;
    for (int n = s; n < e; n++) {
        float h = g_agg[(size_t)n * H + c];
        float wv = g_w[n];
        sum = fmaf(h, wv, sum);
        mx = fmaxf(mx, h);
    }
    atomicAdd(&out[g * (2 * H) + c], sum);
    atomicMax((int*)&out[g * (2 * H) + H + c], __float_as_int(mx));  // relu >= 0
}

extern "C" void kernel_launch(void* const* d_in, const int* in_sizes, int n_in,
                              void* d_out, int out_size) {
    const float* node = (const float*)d_in[0];
    const int* src = (const int*)d_in[1];
    const int* dst = (const int*)d_in[2];
    const int* gid = (const int*)d_in[3];
    const float* W1 = (const float*)d_in[4];
    const float* b1 = (const float*)d_in[5];
    const float* W2 = (const float*)d_in[6];
    const float* b2 = (const float*)d_in[7];
    const float* W3 = (const float*)d_in[8];
    const float* b3 = (const float*)d_in[9];
    const float* Wp = (const float*)d_in[10];
    const float* bp = (const float*)d_in[11];
    float* out = (float*)d_out;

    int N = in_sizes[0] / H;
    int E = in_sizes[1];

    int initn = (out_size > N) ? out_size : N;
    k_init<<<(initn + 255) / 256, 256>>>(out, out_size, N);
    k_deg<<<(E + 255) / 256, 256>>>(src, dst, E);
    k_norm<<<(N + 255) / 256, 256>>>(N);

    int NB = (N + SCAN_CHUNK - 1) / SCAN_CHUNK;
    k_scan1<<<NB, 256>>>(N);
    k_scan2<<<1, MAXBLK>>>(NB, N);
    k_scan3<<<NB, 256>>>(N);
    k_fill<<<(E + 255) / 256, 256>>>(src, dst, E);

    int gb = (N + H - 1) / H;
    int wb = (N * 32 + 255) / 256;

    // layer 1
    k_gemm<<<gb, 256>>>(node, W1, nullptr, N, 0);
    k_gather<<<wb, 256>>>(N, 0, nullptr, nullptr, nullptr);
    // layer 2
    k_gemm<<<gb, 256>>>(nullptr, W2, b1, N, 1);
    k_gather<<<wb, 256>>>(N, 0, nullptr, nullptr, nullptr);
    // layer 3
    k_gemm<<<gb, 256>>>(nullptr, W3, b2, N, 1);
    k_gather<<<wb, 256>>>(N, 1, b3, Wp, bp);   // fused epilogue + gate

    // pooling
    k_pool<<<NGRAPH * SPLITS, 128>>>(gid, N, out);
}